// round 6
// baseline (speedup 1.0000x reference)
#include <cuda_runtime.h>
#include <cstdint>

// Problem constants (fixed shapes: N=2048, F=512, E=32)
#define FDIM 512
#define EDIM 32
#define NWARPS 12
#define NTHREADS (NWARPS * 32)
#define QTILE 4
#define ROWPAD 36          // padded SMEM row stride (floats) -> conflict-free LDS.128
#define NEG_INF (__int_as_float(0xff800000))

__device__ __forceinline__ float warpMax(float v) {
#pragma unroll
    for (int o = 16; o; o >>= 1) v = fmaxf(v, __shfl_xor_sync(0xffffffffu, v, o));
    return v;
}
__device__ __forceinline__ float warpSum(float v) {
#pragma unroll
    for (int o = 16; o; o >>= 1) v += __shfl_xor_sync(0xffffffffu, v, o);
    return v;
}

// Shared layout (floats):
//   FXc    : FDIM*ROWPAD        = 18432   compacted FX, row-major [i][e], 36-float stride
//   sscore : NWARPS*QTILE*FDIM  = 24576   per-(warp,qtile) score rows
//   wsum   : FDIM               = 512     sum_q attn[q,k] accumulator
//   bsel   : EDIM               = 32      xs_b[idx_n, :]
//   fxs    : EDIM               = 32      output accumulator
//   vlist  : FDIM ints                    compacted valid-key indices
//   sints  : 2 ints                       [0]=cnt, [1]=idx
#define SMEM_FLOATS (FDIM*ROWPAD + NWARPS*QTILE*FDIM + FDIM + EDIM + EDIM)
#define SMEM_BYTES  (SMEM_FLOATS*4 + (FDIM + 2)*4)

__global__ __launch_bounds__(NTHREADS, 1)
void model_simple_kernel(const float* __restrict__ X,
                         const float* __restrict__ Xi,
                         const float* __restrict__ Ioh,
                         const float* __restrict__ S,
                         const float* __restrict__ xi_w,
                         const float* __restrict__ xi_b,
                         const float* __restrict__ xs_w,
                         const float* __restrict__ xs_b,
                         float* __restrict__ out)
{
    extern __shared__ float smem[];
    float* FXc    = smem;                        // FDIM*ROWPAD
    float* sscore = FXc + FDIM * ROWPAD;         // NWARPS*QTILE*FDIM
    float* wsum   = sscore + NWARPS * QTILE * FDIM;  // FDIM
    float* bsel   = wsum + FDIM;                 // EDIM
    float* fxs    = bsel + EDIM;                 // EDIM
    int*   vlist  = (int*)(fxs + EDIM);          // FDIM
    int*   sints  = vlist + FDIM;                // 2

    const int n    = blockIdx.x;
    const int tid  = threadIdx.x;
    const int lane = tid & 31;
    const int wid  = tid >> 5;

    // ---- init + find one-hot index ----
    for (int i = tid; i < FDIM; i += NTHREADS) wsum[i] = 0.f;
    if (tid < EDIM) fxs[tid] = 0.f;
    for (int f = tid; f < FDIM; f += NTHREADS)
        if (Ioh[(size_t)n * FDIM + f] != 0.f) sints[1] = f;   // exactly one nonzero
    __syncthreads();

    // ---- deterministic compaction of valid keys (warp 0); bsel gather (warp 1) ----
    if (wid == 0) {
        int c = 0;
        for (int base = 0; base < FDIM; base += 32) {
            float sv = S[(size_t)n * FDIM + base + lane];
            unsigned b = __ballot_sync(0xffffffffu, sv != 0.f);
            if (sv != 0.f) vlist[c + __popc(b & ((1u << lane) - 1u))] = base + lane;
            c += __popc(b);
        }
        if (lane == 0) sints[0] = c;
    } else if (wid == 1) {
        bsel[lane] = xs_b[sints[1] * EDIM + lane];
    }
    __syncthreads();

    const int cnt  = sints[0];             // >= 1 (S[:,0]=1 guaranteed)
    const int jmax = (cnt + 31) >> 5;

    // ---- build compacted FX: FXc[i][e] = X[n,k_i]*xs_w[k_i,e] + xs_b[k_i,e] + bsel[e] ----
    for (int i = tid; i < cnt; i += NTHREADS) {
        int k = vlist[i];
        float x = X[(size_t)n * FDIM + k];
        const float4* w4 = (const float4*)(xs_w + k * EDIM);
        const float4* b4 = (const float4*)(xs_b + k * EDIM);
        float4* dst = (float4*)(FXc + i * ROWPAD);
#pragma unroll
        for (int e4 = 0; e4 < 8; e4++) {
            float4 w = w4[e4], b = b4[e4];
            float4 o;
            o.x = fmaf(x, w.x, b.x) + bsel[e4 * 4 + 0];
            o.y = fmaf(x, w.y, b.y) + bsel[e4 * 4 + 1];
            o.z = fmaf(x, w.z, b.z) + bsel[e4 * 4 + 2];
            o.w = fmaf(x, w.w, b.w) + bsel[e4 * 4 + 3];
            dst[e4] = o;
        }
    }
    // zero-pad tail rows up to the 32-multiple so garbage never enters scores
    for (int i = cnt + tid; i < (jmax << 5); i += NTHREADS) {
        float4* dst = (float4*)(FXc + i * ROWPAD);
#pragma unroll
        for (int e4 = 0; e4 < 8; e4++) dst[e4] = make_float4(0.f, 0.f, 0.f, 0.f);
    }
    __syncthreads();

    const float SCALE = 0.17677669529663687f;  // 1/sqrt(32)

    // ---- attention: each warp owns QTILE=4 queries at a time ----
    for (int i0 = wid * QTILE; i0 < cnt; i0 += NWARPS * QTILE) {
        const int nq = min(QTILE, cnt - i0);
        float q[QTILE][EDIM];
#pragma unroll
        for (int qq = 0; qq < QTILE; qq++) {
            int iq = (qq < nq) ? (i0 + qq) : i0;    // clamp dup; excluded later
            const float4* s4 = (const float4*)(FXc + iq * ROWPAD);
#pragma unroll
            for (int e4 = 0; e4 < 8; e4++) {
                float4 v = s4[e4];
                q[qq][e4 * 4 + 0] = v.x * SCALE;
                q[qq][e4 * 4 + 1] = v.y * SCALE;
                q[qq][e4 * 4 + 2] = v.z * SCALE;
                q[qq][e4 * 4 + 3] = v.w * SCALE;
            }
        }
        float* sc0 = sscore + ((wid * QTILE + 0) << 9);
        float* sc1 = sscore + ((wid * QTILE + 1) << 9);
        float* sc2 = sscore + ((wid * QTILE + 2) << 9);
        float* sc3 = sscore + ((wid * QTILE + 3) << 9);

        float m0 = NEG_INF, m1 = NEG_INF, m2 = NEG_INF, m3 = NEG_INF;
        // pass 1: dots
        for (int j = 0; j < jmax; j++) {
            int k = (j << 5) + lane;
            const float4* kr = (const float4*)(FXc + k * ROWPAD);
            float s0 = 0.f, s1 = 0.f, s2 = 0.f, s3 = 0.f;
#pragma unroll
            for (int e4 = 0; e4 < 8; e4++) {
                float4 kv = kr[e4];
                s0 = fmaf(q[0][e4 * 4 + 0], kv.x, s0);
                s0 = fmaf(q[0][e4 * 4 + 1], kv.y, s0);
                s0 = fmaf(q[0][e4 * 4 + 2], kv.z, s0);
                s0 = fmaf(q[0][e4 * 4 + 3], kv.w, s0);
                s1 = fmaf(q[1][e4 * 4 + 0], kv.x, s1);
                s1 = fmaf(q[1][e4 * 4 + 1], kv.y, s1);
                s1 = fmaf(q[1][e4 * 4 + 2], kv.z, s1);
                s1 = fmaf(q[1][e4 * 4 + 3], kv.w, s1);
                s2 = fmaf(q[2][e4 * 4 + 0], kv.x, s2);
                s2 = fmaf(q[2][e4 * 4 + 1], kv.y, s2);
                s2 = fmaf(q[2][e4 * 4 + 2], kv.z, s2);
                s2 = fmaf(q[2][e4 * 4 + 3], kv.w, s2);
                s3 = fmaf(q[3][e4 * 4 + 0], kv.x, s3);
                s3 = fmaf(q[3][e4 * 4 + 1], kv.y, s3);
                s3 = fmaf(q[3][e4 * 4 + 2], kv.z, s3);
                s3 = fmaf(q[3][e4 * 4 + 3], kv.w, s3);
            }
            bool val = k < cnt;
            s0 = val ? s0 : NEG_INF;
            s1 = val ? s1 : NEG_INF;
            s2 = val ? s2 : NEG_INF;
            s3 = val ? s3 : NEG_INF;
            sc0[k] = s0; sc1[k] = s1; sc2[k] = s2; sc3[k] = s3;
            m0 = fmaxf(m0, s0); m1 = fmaxf(m1, s1);
            m2 = fmaxf(m2, s2); m3 = fmaxf(m3, s3);
        }
        m0 = warpMax(m0); m1 = warpMax(m1); m2 = warpMax(m2); m3 = warpMax(m3);

        // pass 2: exp + sum
        float u0 = 0.f, u1 = 0.f, u2 = 0.f, u3 = 0.f;
        for (int j = 0; j < jmax; j++) {
            int k = (j << 5) + lane;
            float e0 = __expf(sc0[k] - m0); sc0[k] = e0; u0 += e0;
            float e1 = __expf(sc1[k] - m1); sc1[k] = e1; u1 += e1;
            float e2 = __expf(sc2[k] - m2); sc2[k] = e2; u2 += e2;
            float e3 = __expf(sc3[k] - m3); sc3[k] = e3; u3 += e3;
        }
        u0 = warpSum(u0); u1 = warpSum(u1); u2 = warpSum(u2); u3 = warpSum(u3);
        float i0v = 1.f / u0;                        // qq=0 always real (nq>=1)
        float i1v = (nq > 1) ? 1.f / u1 : 0.f;
        float i2v = (nq > 2) ? 1.f / u2 : 0.f;
        float i3v = (nq > 3) ? 1.f / u3 : 0.f;

        // pass 3: accumulate w[k] = sum_q attn[q,k]
        for (int j = 0; j < jmax; j++) {
            int k = (j << 5) + lane;
            if (k < cnt) {
                float t = sc0[k] * i0v + sc1[k] * i1v + sc2[k] * i2v + sc3[k] * i3v;
                atomicAdd(&wsum[k], t);
            }
        }
    }
    __syncthreads();

    // ---- Fxs[e] = sum_k w[k] * FXc[k][e] ----
    {
        float acc = 0.f;
        for (int k = wid; k < cnt; k += NWARPS)
            acc += wsum[k] * FXc[k * ROWPAD + lane];
        atomicAdd(&fxs[lane], acc);
    }
    __syncthreads();

    // ---- epilogue (warp 0) ----
    if (wid == 0) {
        int idx = sints[1];
        float f  = fxs[lane] / (float)cnt;
        float iw = xi_w[idx * EDIM + lane];
        float ib = xi_b[idx * EDIM + lane];
        float t0 = warpSum(ib * f);           // Xi = 0 branch
        float t1 = warpSum((iw + ib) * f);    // Xi = 1 branch
        if (lane == 0) {
            float xi = Xi[n];
            float ul = t0 + xi * (t1 - t0);   // sum(Fxi * Fxs)
            float M  = fmaxf(t0, t1);
            float lz = M + logf(__expf(t0 - M) + __expf(t1 - M));
            out[n] = ul - lz;
        }
    }
}

extern "C" void kernel_launch(void* const* d_in, const int* in_sizes, int n_in,
                              void* d_out, int out_size)
{
    const float* X    = (const float*)d_in[0];
    const float* Xi   = (const float*)d_in[1];
    const float* Ioh  = (const float*)d_in[2];
    const float* S    = (const float*)d_in[3];
    const float* xi_w = (const float*)d_in[4];
    const float* xi_b = (const float*)d_in[5];
    const float* xs_w = (const float*)d_in[6];
    const float* xs_b = (const float*)d_in[7];
    float* out = (float*)d_out;

    const int N = in_sizes[1];  // Xi length = batch

    // Unconditional (no static guard): non-stream host API, capture-safe, idempotent.
    cudaFuncSetAttribute(model_simple_kernel,
                         cudaFuncAttributeMaxDynamicSharedMemorySize, SMEM_BYTES);

    model_simple_kernel<<<N, NTHREADS, SMEM_BYTES>>>(
        X, Xi, Ioh, S, xi_w, xi_b, xs_w, xs_b, out);
}